// round 15
// baseline (speedup 1.0000x reference)
#include <cuda_runtime.h>
#include <cuda_fp16.h>
#include <cstdint>

// Problem constants
#define BB 64
#define SS 4096
#define HH 256
#define AA 128
#define NTOK (BB * SS)          // 262144 tokens

#define PADK 72                 // fp16 elems per smem row (144B, conflict-free)
#define NPART 8                 // context partial slices per batch

// ---------------- scratch (device globals; no allocation allowed) ----------
__device__ float g_scores[NTOK];                    // [B,S] pre-entmax scores
__device__ float g_partial[BB * NPART * HH];        // context partials
__device__ int   g_nzidx[NTOK];                     // compacted support idx
__device__ float g_nzw[NTOK];                       // compacted support w
__device__ int   g_nzcnt[BB];                       // support count per batch
__device__ int   g_ctr[BB];                         // ctx slice arrival counter
// W1 pre-converted to fp16, padded chunk layout: [4 chunks][128 n][72]
__device__ __half g_Bh[4 * 128 * PADK];

// ---------------- PTX helpers ----------------------------------------------
__device__ __forceinline__ uint32_t s2u(const void* p) {
    uint32_t a;
    asm("{ .reg .u64 t; cvta.to.shared.u64 t, %1; cvt.u32.u64 %0, t; }"
        : "=r"(a) : "l"(p));
    return a;
}

#define LDSM_X4(r0, r1, r2, r3, addr)                                        \
    asm volatile("ldmatrix.sync.aligned.m8n8.x4.shared.b16 {%0,%1,%2,%3}, [%4];" \
                 : "=r"(r0), "=r"(r1), "=r"(r2), "=r"(r3) : "r"(addr))

#define MMA_FP16(d0, d1, d2, d3, a0, a1, a2, a3, b0, b1)                     \
    asm volatile("mma.sync.aligned.m16n8k16.row.col.f32.f16.f16.f32 "       \
                 "{%0,%1,%2,%3}, {%4,%5,%6,%7}, {%8,%9}, {%0,%1,%2,%3};"     \
                 : "+f"(d0), "+f"(d1), "+f"(d2), "+f"(d3)                    \
                 : "r"(a0), "r"(a1), "r"(a2), "r"(a3), "r"(b0), "r"(b1))

#define CP_ASYNC16(dst, src)                                                 \
    asm volatile("cp.async.cg.shared.global [%0], [%1], 16;"                 \
                 :: "r"(dst), "l"(src))
#define CP_COMMIT() asm volatile("cp.async.commit_group;" ::: "memory")
#define CP_WAIT0()  asm volatile("cp.async.wait_group 0;" ::: "memory")

__device__ __forceinline__ float ldcg_f32(const float* p) {
    float v;
    asm volatile("ld.global.cg.f32 %0, [%1];" : "=f"(v) : "l"(p));
    return v;
}

// fast tanh: (e^{2x}-1)/(e^{2x}+1); clamp keeps e finite; abs err ~1e-6.
// Validated in R14: rel_err identical to tanhf at the 5th digit.
__device__ __forceinline__ float fast_tanh(float x) {
    x = fminf(fmaxf(x, -15.0f), 15.0f);
    const float e = __expf(2.0f * x);
    return (e - 1.0f) * __frcp_rn(e + 1.0f);
}

// ============================================================================
// Kernel 0: convert W1 [256,128] fp32 -> fp16, padded chunk layout.
// ============================================================================
__global__ __launch_bounds__(256) void convW_kernel(const float* __restrict__ W1)
{
    const int idx = blockIdx.x * 256 + threadIdx.x;   // 0..32767
    const int k = idx >> 7;       // H index 0..255
    const int n = idx & 127;      // A index 0..127
    const float w = W1[idx];
    const int chunk = k >> 6;
    const int kc = k & 63;
    const int pos = (chunk * 128 + n) * PADK + kc;
    g_Bh[pos] = __float2half_rn(w);
}

// ============================================================================
// Kernel 1: scores GEMM via single-term fp16 mma.sync (R13 structure —
// single buffer, short register live-ranges; cross-CTA overlap at 2 CTAs/SM).
// One CTA per 128 tokens; 8 warps, warp tile m32 x n64. 16 MMA/warp/kstep.
// ============================================================================
#define OFF_A     0
#define OFF_B     18432
#define OFF_B1S   36864
#define OFF_W2S   37376
#define OFF_SRED  37888
#define SMEM_BYTES 38912

__global__ __launch_bounds__(256, 2) void scores_mma_kernel(
    const float* __restrict__ X,    // [NTOK, 256]
    const float* __restrict__ b1,   // [128]
    const float* __restrict__ W2,   // [128]
    const float* __restrict__ b2)   // [1]
{
    extern __shared__ __align__(16) char smem[];
    const uint32_t sb = s2u(smem);
    const int tid = threadIdx.x;
    const int wid = tid >> 5;
    const int lane = tid & 31;
    const int tok0 = blockIdx.x * 128;

    const int wm = (wid >> 1) * 32;   // warp M origin (0,32,64,96)
    const int wn = (wid & 1) * 64;    // warp N origin (0,64)

    if (tid < 128) {
        *(float*)(smem + OFF_B1S + tid * 4) = b1[tid];
        *(float*)(smem + OFF_W2S + tid * 4) = W2[tid];
    }

    float acc[2][8][4];
#pragma unroll
    for (int mi = 0; mi < 2; mi++)
#pragma unroll
        for (int nf = 0; nf < 8; nf++)
#pragma unroll
            for (int i = 0; i < 4; i++) acc[mi][nf][i] = 0.0f;

    const int row  = tid >> 1;      // 0..127 (token row in tile)
    const int half = tid & 1;       // 32-col half of the 64-col chunk
    const float4* Xr = (const float4*)(X + (size_t)(tok0 + row) * HH);
    const uint32_t a_boff = (uint32_t)row * (PADK * 2) + (uint32_t)(half * 64);

    const int grp = lane >> 3;
    const uint32_t a_rowl = (uint32_t)((lane & 7) + (grp & 1) * 8);
    const uint32_t a_kad = (uint32_t)((grp >> 1) * 8) * 2;
    const uint32_t b_rowbase = (uint32_t)((lane & 7) + (grp >> 1) * 8);
    const uint32_t b_kad = (uint32_t)((grp & 1) * 8) * 2;

    float4 v[8];
#pragma unroll
    for (int q = 0; q < 8; q++) v[q] = Xr[half * 8 + q];

    for (int c = 0; c < 4; c++) {
        // ---- B chunk via cp.async (18432B) ----
        {
            const char* srcb = (const char*)(g_Bh + c * 128 * PADK);
#pragma unroll
            for (int i = 0; i < 5; i++) {
                const int idx = tid + i * 256;
                if (idx < 1152)
                    CP_ASYNC16(sb + OFF_B + idx * 16, srcb + idx * 16);
            }
            CP_COMMIT();
        }
        // ---- convert staged A chunk -> fp16 ----
        {
#pragma unroll
            for (int q = 0; q < 8; q++) {
                const float4 vv = v[q];
                const __half2 h0 = __floats2half2_rn(vv.x, vv.y);
                const __half2 h1 = __floats2half2_rn(vv.z, vv.w);
                uint2 hw;
                hw.x = *(const uint32_t*)&h0;
                hw.y = *(const uint32_t*)&h1;
                *(uint2*)(smem + OFF_A + a_boff + (uint32_t)(q * 8)) = hw;
            }
        }
        if (c < 3) {
#pragma unroll
            for (int q = 0; q < 8; q++) v[q] = Xr[(c + 1) * 16 + half * 8 + q];
        }
        CP_WAIT0();
        __syncthreads();

        // ---- 4 k-steps of 16, 16 MMA each ----
#pragma unroll
        for (int ks = 0; ks < 4; ks++) {
            const uint32_t k0b = (uint32_t)(ks * 16) * 2;
            uint32_t ah[2][4];
#pragma unroll
            for (int mi = 0; mi < 2; mi++) {
                const uint32_t a_off =
                    ((uint32_t)(wm + mi * 16) + a_rowl) * (PADK * 2) + k0b + a_kad;
                LDSM_X4(ah[mi][0], ah[mi][1], ah[mi][2], ah[mi][3],
                        sb + OFF_A + a_off);
            }
#pragma unroll
            for (int ng = 0; ng < 4; ng++) {
                const uint32_t b_off =
                    ((uint32_t)(wn + ng * 16) + b_rowbase) * (PADK * 2) + k0b + b_kad;
                uint32_t bh0, bh1, bh2, bh3;
                LDSM_X4(bh0, bh1, bh2, bh3, sb + OFF_B + b_off);
#pragma unroll
                for (int mi = 0; mi < 2; mi++) {
                    float* d0 = acc[mi][ng * 2];
                    float* d1 = acc[mi][ng * 2 + 1];
                    MMA_FP16(d0[0], d0[1], d0[2], d0[3],
                             ah[mi][0], ah[mi][1], ah[mi][2], ah[mi][3], bh0, bh1);
                    MMA_FP16(d1[0], d1[1], d1[2], d1[3],
                             ah[mi][0], ah[mi][1], ah[mi][2], ah[mi][3], bh2, bh3);
                }
            }
        }
        __syncthreads();
    }

    // ---- epilogue: fast-tanh dot W2 over warp's 64 cols, cross-warp add ----
    float* sred = (float*)(smem + OFF_SRED);   // [2][128]
#pragma unroll
    for (int mi = 0; mi < 2; mi++) {
        float s0 = 0.0f, s1 = 0.0f;
#pragma unroll
        for (int nf = 0; nf < 8; nf++) {
            const int c0 = wn + nf * 8 + (lane & 3) * 2;
            const float bb0 = *(const float*)(smem + OFF_B1S + c0 * 4);
            const float bb1v = *(const float*)(smem + OFF_B1S + (c0 + 1) * 4);
            const float ww0 = *(const float*)(smem + OFF_W2S + c0 * 4);
            const float ww1 = *(const float*)(smem + OFF_W2S + (c0 + 1) * 4);
            s0 += fast_tanh(acc[mi][nf][0] + bb0) * ww0 +
                  fast_tanh(acc[mi][nf][1] + bb1v) * ww1;
            s1 += fast_tanh(acc[mi][nf][2] + bb0) * ww0 +
                  fast_tanh(acc[mi][nf][3] + bb1v) * ww1;
        }
        s0 += __shfl_xor_sync(0xffffffffu, s0, 1);
        s0 += __shfl_xor_sync(0xffffffffu, s0, 2);
        s1 += __shfl_xor_sync(0xffffffffu, s1, 1);
        s1 += __shfl_xor_sync(0xffffffffu, s1, 2);
        if ((lane & 3) == 0) {
            const int r = wm + mi * 16 + (lane >> 2);
            sred[(wid & 1) * 128 + r]     = s0;
            sred[(wid & 1) * 128 + r + 8] = s1;
        }
    }
    __syncthreads();
    if (tid < 128)
        g_scores[tok0 + tid] = sred[tid] + sred[128 + tid] + b2[0];
}

// ============================================================================
// Kernel 2: entmax-1.5 per batch row via fixed-count bisection (no sort)
// + deterministic support compaction to global. Also resets g_ctr[b].
// ============================================================================
__global__ __launch_bounds__(512) void entmax_kernel(float* __restrict__ weights)
{
    const int b = blockIdx.x;
    const int tid = threadIdx.x;
    const int wid = tid >> 5;
    const int lane = tid & 31;

    __shared__ float red[16];
    __shared__ float s_bc;
    __shared__ int iscan[512];

    if (tid == 0) g_ctr[b] = 0;     // reset ctx arrival counter each replay

    const float* sc = g_scores + (size_t)b * SS;
    const int base = tid * 8;

    float z[8];
    {
        const float4 p0 = ((const float4*)sc)[tid * 2];
        const float4 p1 = ((const float4*)sc)[tid * 2 + 1];
        z[0] = 0.5f * p0.x; z[1] = 0.5f * p0.y;
        z[2] = 0.5f * p0.z; z[3] = 0.5f * p0.w;
        z[4] = 0.5f * p1.x; z[5] = 0.5f * p1.y;
        z[6] = 0.5f * p1.z; z[7] = 0.5f * p1.w;
    }

    float m = z[0];
#pragma unroll
    for (int j = 1; j < 8; j++) m = fmaxf(m, z[j]);
#pragma unroll
    for (int o = 16; o > 0; o >>= 1) m = fmaxf(m, __shfl_xor_sync(0xffffffffu, m, o));
    if (lane == 0) red[wid] = m;
    __syncthreads();
    if (tid == 0) {
        float t = red[0];
#pragma unroll
        for (int i = 1; i < 16; i++) t = fmaxf(t, red[i]);
        s_bc = t;
    }
    __syncthreads();
    const float mx = s_bc;
#pragma unroll
    for (int j = 0; j < 8; j++) z[j] -= mx;

    float lo = -1.0f, hi = 0.0f;
    for (int it = 0; it < 30; it++) {
        const float mid = 0.5f * (lo + hi);
        float s = 0.0f;
#pragma unroll
        for (int j = 0; j < 8; j++) {
            float d = z[j] - mid;
            d = d > 0.0f ? d : 0.0f;
            s = fmaf(d, d, s);
        }
#pragma unroll
        for (int o = 16; o > 0; o >>= 1) s += __shfl_xor_sync(0xffffffffu, s, o);
        if (lane == 0) red[wid] = s;
        __syncthreads();
        float tot = 0.0f;
#pragma unroll
        for (int i = 0; i < 16; i++) tot += red[i];
        __syncthreads();
        if (tot >= 1.0f) lo = mid; else hi = mid;
    }
    const float tau = 0.5f * (lo + hi);

    float* wout = weights + (size_t)b * SS;
    float wv[8];
    int mycnt = 0;
#pragma unroll
    for (int j = 0; j < 8; j++) {
        float d = z[j] - tau;
        d = d > 0.0f ? d : 0.0f;
        const float w = d * d;
        wv[j] = w;
        wout[base + j] = w;
        if (w > 0.0f) mycnt++;
    }
    iscan[tid] = mycnt;
    __syncthreads();
    for (int off = 1; off < 512; off <<= 1) {
        int a = 0;
        if (tid >= off) a = iscan[tid - off];
        __syncthreads();
        iscan[tid] += a;
        __syncthreads();
    }
    int pos = iscan[tid] - mycnt;
#pragma unroll
    for (int j = 0; j < 8; j++) {
        if (wv[j] > 0.0f) {
            g_nzidx[(size_t)b * SS + pos] = base + j;
            g_nzw[(size_t)b * SS + pos]   = wv[j];
            pos++;
        }
    }
    if (tid == 511) g_nzcnt[b] = iscan[511];
}

// ============================================================================
// Kernel 3: sparse context partials + last-block fused reduce.
// grid (B, NPART), 256 threads (one per h).
// ============================================================================
__global__ __launch_bounds__(256) void ctx_sparse_kernel(
    const float* __restrict__ X, float* __restrict__ ctx)
{
    const int b = blockIdx.x;
    const int sl = blockIdx.y;
    const int h = threadIdx.x;

    __shared__ int   sidx[576];
    __shared__ float swt[576];
    __shared__ int   s_last;

    const int cnt = g_nzcnt[b];
    const int per = (cnt + NPART - 1) / NPART;
    const int s0 = sl * per;
    int s1 = s0 + per; if (s1 > cnt) s1 = cnt;
    const int n = s1 - s0;

    for (int t = h; t < n; t += 256) {
        sidx[t] = g_nzidx[(size_t)b * SS + s0 + t];
        swt[t]  = g_nzw[(size_t)b * SS + s0 + t];
    }
    __syncthreads();

    const float* Xb = X + (size_t)b * SS * HH;
    float acc = 0.0f;
    int i = 0;
    for (; i + 8 <= n; i += 8) {
        float x[8];
#pragma unroll
        for (int j = 0; j < 8; j++)
            x[j] = Xb[(size_t)sidx[i + j] * HH + h];
#pragma unroll
        for (int j = 0; j < 8; j++)
            acc = fmaf(x[j], swt[i + j], acc);
    }
    for (; i < n; i++)
        acc = fmaf(Xb[(size_t)sidx[i] * HH + h], swt[i], acc);

    g_partial[((size_t)b * NPART + sl) * HH + h] = acc;

    // last-arriving block for this batch reduces all NPART partials
    __threadfence();
    __syncthreads();
    if (h == 0) {
        const int old = atomicAdd(&g_ctr[b], 1);
        s_last = (old == NPART - 1) ? 1 : 0;
    }
    __syncthreads();
    if (s_last) {
        float s = 0.0f;
#pragma unroll
        for (int c = 0; c < NPART; c++)
            s += ldcg_f32(&g_partial[((size_t)b * NPART + c) * HH + h]);
        ctx[(size_t)b * HH + h] = s;
    }
}

// ============================================================================
extern "C" void kernel_launch(void* const* d_in, const int* in_sizes, int n_in,
                              void* d_out, int out_size)
{
    const float* X  = (const float*)d_in[0];   // [64,4096,256]
    const float* W1 = (const float*)d_in[1];   // [256,128]
    const float* b1 = (const float*)d_in[2];   // [128]
    const float* W2 = (const float*)d_in[3];   // [128,1]
    const float* b2 = (const float*)d_in[4];   // [1]

    float* out = (float*)d_out;
    float* ctx = out;                 // [64,256]  (tuple elem 0)
    float* wts = out + BB * HH;       // [64,4096] (tuple elem 1)

    cudaFuncSetAttribute(scores_mma_kernel,
                         cudaFuncAttributeMaxDynamicSharedMemorySize, SMEM_BYTES);

    convW_kernel<<<128, 256>>>(W1);
    scores_mma_kernel<<<NTOK / 128, 256, SMEM_BYTES>>>(X, b1, W2, b2);
    entmax_kernel<<<BB, 512>>>(wts);
    ctx_sparse_kernel<<<dim3(BB, NPART), 256>>>(X, ctx);
}

// round 16
// speedup vs baseline: 1.1306x; 1.1306x over previous
#include <cuda_runtime.h>
#include <cuda_fp16.h>
#include <cstdint>

// Problem constants
#define BB 64
#define SS 4096
#define HH 256
#define AA 128
#define NTOK (BB * SS)          // 262144 tokens

#define PADK 72                 // fp16 elems per smem row (144B, conflict-free)
#define NPART 8                 // context partial slices per batch

// ---------------- scratch (device globals; no allocation allowed) ----------
__device__ float g_scores[NTOK];                    // [B,S] pre-entmax scores
__device__ float g_partial[BB * NPART * HH];        // context partials
__device__ int   g_nzidx[NTOK];                     // compacted support idx
__device__ float g_nzw[NTOK];                       // compacted support w
__device__ int   g_nzcnt[BB];                       // support count per batch
__device__ int   g_ctr[BB];                         // ctx slice arrival counter
// W1 pre-converted to fp16, padded chunk layout: [4 chunks][128 n][72]
__device__ __half g_Bh[4 * 128 * PADK];

// ---------------- PTX helpers ----------------------------------------------
__device__ __forceinline__ uint32_t s2u(const void* p) {
    uint32_t a;
    asm("{ .reg .u64 t; cvta.to.shared.u64 t, %1; cvt.u32.u64 %0, t; }"
        : "=r"(a) : "l"(p));
    return a;
}

#define LDSM_X4(r0, r1, r2, r3, addr)                                        \
    asm volatile("ldmatrix.sync.aligned.m8n8.x4.shared.b16 {%0,%1,%2,%3}, [%4];" \
                 : "=r"(r0), "=r"(r1), "=r"(r2), "=r"(r3) : "r"(addr))

#define MMA_FP16(d0, d1, d2, d3, a0, a1, a2, a3, b0, b1)                     \
    asm volatile("mma.sync.aligned.m16n8k16.row.col.f32.f16.f16.f32 "       \
                 "{%0,%1,%2,%3}, {%4,%5,%6,%7}, {%8,%9}, {%0,%1,%2,%3};"     \
                 : "+f"(d0), "+f"(d1), "+f"(d2), "+f"(d3)                    \
                 : "r"(a0), "r"(a1), "r"(a2), "r"(a3), "r"(b0), "r"(b1))

#define CP_ASYNC16(dst, src)                                                 \
    asm volatile("cp.async.cg.shared.global [%0], [%1], 16;"                 \
                 :: "r"(dst), "l"(src))
#define CP_COMMIT() asm volatile("cp.async.commit_group;" ::: "memory")
#define CP_WAIT0()  asm volatile("cp.async.wait_group 0;" ::: "memory")

__device__ __forceinline__ float ldcg_f32(const float* p) {
    float v;
    asm volatile("ld.global.cg.f32 %0, [%1];" : "=f"(v) : "l"(p));
    return v;
}

// ============================================================================
// Kernel 0: convert W1 [256,128] fp32 -> fp16, padded chunk layout.
// ============================================================================
__global__ __launch_bounds__(256) void convW_kernel(const float* __restrict__ W1)
{
    const int idx = blockIdx.x * 256 + threadIdx.x;   // 0..32767
    const int k = idx >> 7;       // H index 0..255
    const int n = idx & 127;      // A index 0..127
    const float w = W1[idx];
    const int chunk = k >> 6;
    const int kc = k & 63;
    const int pos = (chunk * 128 + n) * PADK + kc;
    g_Bh[pos] = __float2half_rn(w);
}

// ============================================================================
// Kernel 1: scores GEMM via single-term fp16 mma.sync (R13 structure —
// single buffer, short register live-ranges; cross-CTA overlap at 2 CTAs/SM;
// library tanhf in the epilogue — measured faster than hand-rolled).
// One CTA per 128 tokens; 8 warps, warp tile m32 x n64. 16 MMA/warp/kstep.
// ============================================================================
#define OFF_A     0
#define OFF_B     18432
#define OFF_B1S   36864
#define OFF_W2S   37376
#define OFF_SRED  37888
#define SMEM_BYTES 38912

__global__ __launch_bounds__(256, 2) void scores_mma_kernel(
    const float* __restrict__ X,    // [NTOK, 256]
    const float* __restrict__ b1,   // [128]
    const float* __restrict__ W2,   // [128]
    const float* __restrict__ b2)   // [1]
{
    extern __shared__ __align__(16) char smem[];
    const uint32_t sb = s2u(smem);
    const int tid = threadIdx.x;
    const int wid = tid >> 5;
    const int lane = tid & 31;
    const int tok0 = blockIdx.x * 128;

    const int wm = (wid >> 1) * 32;   // warp M origin (0,32,64,96)
    const int wn = (wid & 1) * 64;    // warp N origin (0,64)

    if (tid < 128) {
        *(float*)(smem + OFF_B1S + tid * 4) = b1[tid];
        *(float*)(smem + OFF_W2S + tid * 4) = W2[tid];
    }

    float acc[2][8][4];
#pragma unroll
    for (int mi = 0; mi < 2; mi++)
#pragma unroll
        for (int nf = 0; nf < 8; nf++)
#pragma unroll
            for (int i = 0; i < 4; i++) acc[mi][nf][i] = 0.0f;

    const int row  = tid >> 1;      // 0..127 (token row in tile)
    const int half = tid & 1;       // 32-col half of the 64-col chunk
    const float4* Xr = (const float4*)(X + (size_t)(tok0 + row) * HH);
    const uint32_t a_boff = (uint32_t)row * (PADK * 2) + (uint32_t)(half * 64);

    const int grp = lane >> 3;
    const uint32_t a_rowl = (uint32_t)((lane & 7) + (grp & 1) * 8);
    const uint32_t a_kad = (uint32_t)((grp >> 1) * 8) * 2;
    const uint32_t b_rowbase = (uint32_t)((lane & 7) + (grp >> 1) * 8);
    const uint32_t b_kad = (uint32_t)((grp & 1) * 8) * 2;

    float4 v[8];
#pragma unroll
    for (int q = 0; q < 8; q++) v[q] = Xr[half * 8 + q];

    for (int c = 0; c < 4; c++) {
        // ---- B chunk via cp.async (18432B) ----
        {
            const char* srcb = (const char*)(g_Bh + c * 128 * PADK);
#pragma unroll
            for (int i = 0; i < 5; i++) {
                const int idx = tid + i * 256;
                if (idx < 1152)
                    CP_ASYNC16(sb + OFF_B + idx * 16, srcb + idx * 16);
            }
            CP_COMMIT();
        }
        // ---- convert staged A chunk -> fp16 ----
        {
#pragma unroll
            for (int q = 0; q < 8; q++) {
                const float4 vv = v[q];
                const __half2 h0 = __floats2half2_rn(vv.x, vv.y);
                const __half2 h1 = __floats2half2_rn(vv.z, vv.w);
                uint2 hw;
                hw.x = *(const uint32_t*)&h0;
                hw.y = *(const uint32_t*)&h1;
                *(uint2*)(smem + OFF_A + a_boff + (uint32_t)(q * 8)) = hw;
            }
        }
        if (c < 3) {
#pragma unroll
            for (int q = 0; q < 8; q++) v[q] = Xr[(c + 1) * 16 + half * 8 + q];
        }
        CP_WAIT0();
        __syncthreads();

        // ---- 4 k-steps of 16, 16 MMA each ----
#pragma unroll
        for (int ks = 0; ks < 4; ks++) {
            const uint32_t k0b = (uint32_t)(ks * 16) * 2;
            uint32_t ah[2][4];
#pragma unroll
            for (int mi = 0; mi < 2; mi++) {
                const uint32_t a_off =
                    ((uint32_t)(wm + mi * 16) + a_rowl) * (PADK * 2) + k0b + a_kad;
                LDSM_X4(ah[mi][0], ah[mi][1], ah[mi][2], ah[mi][3],
                        sb + OFF_A + a_off);
            }
#pragma unroll
            for (int ng = 0; ng < 4; ng++) {
                const uint32_t b_off =
                    ((uint32_t)(wn + ng * 16) + b_rowbase) * (PADK * 2) + k0b + b_kad;
                uint32_t bh0, bh1, bh2, bh3;
                LDSM_X4(bh0, bh1, bh2, bh3, sb + OFF_B + b_off);
#pragma unroll
                for (int mi = 0; mi < 2; mi++) {
                    float* d0 = acc[mi][ng * 2];
                    float* d1 = acc[mi][ng * 2 + 1];
                    MMA_FP16(d0[0], d0[1], d0[2], d0[3],
                             ah[mi][0], ah[mi][1], ah[mi][2], ah[mi][3], bh0, bh1);
                    MMA_FP16(d1[0], d1[1], d1[2], d1[3],
                             ah[mi][0], ah[mi][1], ah[mi][2], ah[mi][3], bh2, bh3);
                }
            }
        }
        __syncthreads();
    }

    // ---- epilogue: tanh dot W2 over warp's 64 cols, then cross-warp add ----
    float* sred = (float*)(smem + OFF_SRED);   // [2][128]
#pragma unroll
    for (int mi = 0; mi < 2; mi++) {
        float s0 = 0.0f, s1 = 0.0f;
#pragma unroll
        for (int nf = 0; nf < 8; nf++) {
            const int c0 = wn + nf * 8 + (lane & 3) * 2;
            const float bb0 = *(const float*)(smem + OFF_B1S + c0 * 4);
            const float bb1v = *(const float*)(smem + OFF_B1S + (c0 + 1) * 4);
            const float ww0 = *(const float*)(smem + OFF_W2S + c0 * 4);
            const float ww1 = *(const float*)(smem + OFF_W2S + (c0 + 1) * 4);
            s0 += tanhf(acc[mi][nf][0] + bb0) * ww0 +
                  tanhf(acc[mi][nf][1] + bb1v) * ww1;
            s1 += tanhf(acc[mi][nf][2] + bb0) * ww0 +
                  tanhf(acc[mi][nf][3] + bb1v) * ww1;
        }
        s0 += __shfl_xor_sync(0xffffffffu, s0, 1);
        s0 += __shfl_xor_sync(0xffffffffu, s0, 2);
        s1 += __shfl_xor_sync(0xffffffffu, s1, 1);
        s1 += __shfl_xor_sync(0xffffffffu, s1, 2);
        if ((lane & 3) == 0) {
            const int r = wm + mi * 16 + (lane >> 2);
            sred[(wid & 1) * 128 + r]     = s0;
            sred[(wid & 1) * 128 + r + 8] = s1;
        }
    }
    __syncthreads();
    if (tid < 128)
        g_scores[tok0 + tid] = sred[tid] + sred[128 + tid] + b2[0];
}

// ============================================================================
// Kernel 2: entmax-1.5 per batch row via fixed-count bisection (no sort)
// + deterministic support compaction to global. Also resets g_ctr[b].
// ============================================================================
__global__ __launch_bounds__(512) void entmax_kernel(float* __restrict__ weights)
{
    const int b = blockIdx.x;
    const int tid = threadIdx.x;
    const int wid = tid >> 5;
    const int lane = tid & 31;

    __shared__ float red[16];
    __shared__ float s_bc;
    __shared__ int iscan[512];

    if (tid == 0) g_ctr[b] = 0;     // reset ctx arrival counter each replay

    const float* sc = g_scores + (size_t)b * SS;
    const int base = tid * 8;

    float z[8];
    {
        const float4 p0 = ((const float4*)sc)[tid * 2];
        const float4 p1 = ((const float4*)sc)[tid * 2 + 1];
        z[0] = 0.5f * p0.x; z[1] = 0.5f * p0.y;
        z[2] = 0.5f * p0.z; z[3] = 0.5f * p0.w;
        z[4] = 0.5f * p1.x; z[5] = 0.5f * p1.y;
        z[6] = 0.5f * p1.z; z[7] = 0.5f * p1.w;
    }

    float m = z[0];
#pragma unroll
    for (int j = 1; j < 8; j++) m = fmaxf(m, z[j]);
#pragma unroll
    for (int o = 16; o > 0; o >>= 1) m = fmaxf(m, __shfl_xor_sync(0xffffffffu, m, o));
    if (lane == 0) red[wid] = m;
    __syncthreads();
    if (tid == 0) {
        float t = red[0];
#pragma unroll
        for (int i = 1; i < 16; i++) t = fmaxf(t, red[i]);
        s_bc = t;
    }
    __syncthreads();
    const float mx = s_bc;
#pragma unroll
    for (int j = 0; j < 8; j++) z[j] -= mx;

    // bisection, 24 iterations: |tau error| <= 2^-24 ~ 6e-8 (weights ~1e-7)
    float lo = -1.0f, hi = 0.0f;
    for (int it = 0; it < 24; it++) {
        const float mid = 0.5f * (lo + hi);
        float s = 0.0f;
#pragma unroll
        for (int j = 0; j < 8; j++) {
            float d = z[j] - mid;
            d = d > 0.0f ? d : 0.0f;
            s = fmaf(d, d, s);
        }
#pragma unroll
        for (int o = 16; o > 0; o >>= 1) s += __shfl_xor_sync(0xffffffffu, s, o);
        if (lane == 0) red[wid] = s;
        __syncthreads();
        float tot = 0.0f;
#pragma unroll
        for (int i = 0; i < 16; i++) tot += red[i];
        __syncthreads();
        if (tot >= 1.0f) lo = mid; else hi = mid;
    }
    const float tau = 0.5f * (lo + hi);

    float* wout = weights + (size_t)b * SS;
    float wv[8];
    int mycnt = 0;
#pragma unroll
    for (int j = 0; j < 8; j++) {
        float d = z[j] - tau;
        d = d > 0.0f ? d : 0.0f;
        const float w = d * d;
        wv[j] = w;
        wout[base + j] = w;
        if (w > 0.0f) mycnt++;
    }
    iscan[tid] = mycnt;
    __syncthreads();
    for (int off = 1; off < 512; off <<= 1) {
        int a = 0;
        if (tid >= off) a = iscan[tid - off];
        __syncthreads();
        iscan[tid] += a;
        __syncthreads();
    }
    int pos = iscan[tid] - mycnt;
#pragma unroll
    for (int j = 0; j < 8; j++) {
        if (wv[j] > 0.0f) {
            g_nzidx[(size_t)b * SS + pos] = base + j;
            g_nzw[(size_t)b * SS + pos]   = wv[j];
            pos++;
        }
    }
    if (tid == 511) g_nzcnt[b] = iscan[511];
}

// ============================================================================
// Kernel 3: sparse context partials + last-block fused reduce.
// grid (B, NPART), 256 threads (one per h).
// ============================================================================
__global__ __launch_bounds__(256) void ctx_sparse_kernel(
    const float* __restrict__ X, float* __restrict__ ctx)
{
    const int b = blockIdx.x;
    const int sl = blockIdx.y;
    const int h = threadIdx.x;

    __shared__ int   sidx[576];
    __shared__ float swt[576];
    __shared__ int   s_last;

    const int cnt = g_nzcnt[b];
    const int per = (cnt + NPART - 1) / NPART;
    const int s0 = sl * per;
    int s1 = s0 + per; if (s1 > cnt) s1 = cnt;
    const int n = s1 - s0;

    for (int t = h; t < n; t += 256) {
        sidx[t] = g_nzidx[(size_t)b * SS + s0 + t];
        swt[t]  = g_nzw[(size_t)b * SS + s0 + t];
    }
    __syncthreads();

    const float* Xb = X + (size_t)b * SS * HH;
    float acc = 0.0f;
    int i = 0;
    for (; i + 8 <= n; i += 8) {
        float x[8];
#pragma unroll
        for (int j = 0; j < 8; j++)
            x[j] = Xb[(size_t)sidx[i + j] * HH + h];
#pragma unroll
        for (int j = 0; j < 8; j++)
            acc = fmaf(x[j], swt[i + j], acc);
    }
    for (; i < n; i++)
        acc = fmaf(Xb[(size_t)sidx[i] * HH + h], swt[i], acc);

    g_partial[((size_t)b * NPART + sl) * HH + h] = acc;

    // last-arriving block for this batch reduces all NPART partials
    __threadfence();
    __syncthreads();
    if (h == 0) {
        const int old = atomicAdd(&g_ctr[b], 1);
        s_last = (old == NPART - 1) ? 1 : 0;
    }
    __syncthreads();
    if (s_last) {
        float s = 0.0f;
#pragma unroll
        for (int c = 0; c < NPART; c++)
            s += ldcg_f32(&g_partial[((size_t)b * NPART + c) * HH + h]);
        ctx[(size_t)b * HH + h] = s;
    }
}

// ============================================================================
extern "C" void kernel_launch(void* const* d_in, const int* in_sizes, int n_in,
                              void* d_out, int out_size)
{
    const float* X  = (const float*)d_in[0];   // [64,4096,256]
    const float* W1 = (const float*)d_in[1];   // [256,128]
    const float* b1 = (const float*)d_in[2];   // [128]
    const float* W2 = (const float*)d_in[3];   // [128,1]
    const float* b2 = (const float*)d_in[4];   // [1]

    float* out = (float*)d_out;
    float* ctx = out;                 // [64,256]  (tuple elem 0)
    float* wts = out + BB * HH;       // [64,4096] (tuple elem 1)

    cudaFuncSetAttribute(scores_mma_kernel,
                         cudaFuncAttributeMaxDynamicSharedMemorySize, SMEM_BYTES);

    convW_kernel<<<128, 256>>>(W1);
    scores_mma_kernel<<<NTOK / 128, 256, SMEM_BYTES>>>(X, b1, W2, b2);
    entmax_kernel<<<BB, 512>>>(wts);
    ctx_sparse_kernel<<<dim3(BB, NPART), 256>>>(X, ctx);
}

// round 17
// speedup vs baseline: 1.1727x; 1.0372x over previous
#include <cuda_runtime.h>
#include <cuda_fp16.h>
#include <cstdint>

// Problem constants
#define BB 64
#define SS 4096
#define HH 256
#define AA 128
#define NTOK (BB * SS)          // 262144 tokens

#define PADK 72                 // fp16 elems per smem row (144B, conflict-free)
#define NPART 8                 // context partial slices per batch

// ---------------- scratch (device globals; no allocation allowed) ----------
__device__ float g_scores[NTOK];                    // [B,S] pre-entmax scores
__device__ float g_partial[BB * NPART * HH];        // context partials
__device__ int   g_nzidx[NTOK];                     // compacted support idx
__device__ float g_nzw[NTOK];                       // compacted support w
__device__ int   g_nzcnt[BB];                       // support count per batch
__device__ int   g_ctr[BB];                         // ctx slice arrival counter
// W1 pre-converted to fp16, padded chunk layout: [4 chunks][128 n][72]
__device__ __half g_Bh[4 * 128 * PADK];

// ---------------- PTX helpers ----------------------------------------------
__device__ __forceinline__ uint32_t s2u(const void* p) {
    uint32_t a;
    asm("{ .reg .u64 t; cvta.to.shared.u64 t, %1; cvt.u32.u64 %0, t; }"
        : "=r"(a) : "l"(p));
    return a;
}

#define LDSM_X4(r0, r1, r2, r3, addr)                                        \
    asm volatile("ldmatrix.sync.aligned.m8n8.x4.shared.b16 {%0,%1,%2,%3}, [%4];" \
                 : "=r"(r0), "=r"(r1), "=r"(r2), "=r"(r3) : "r"(addr))

#define MMA_FP16(d0, d1, d2, d3, a0, a1, a2, a3, b0, b1)                     \
    asm volatile("mma.sync.aligned.m16n8k16.row.col.f32.f16.f16.f32 "       \
                 "{%0,%1,%2,%3}, {%4,%5,%6,%7}, {%8,%9}, {%0,%1,%2,%3};"     \
                 : "+f"(d0), "+f"(d1), "+f"(d2), "+f"(d3)                    \
                 : "r"(a0), "r"(a1), "r"(a2), "r"(a3), "r"(b0), "r"(b1))

#define CP_ASYNC16(dst, src)                                                 \
    asm volatile("cp.async.cg.shared.global [%0], [%1], 16;"                 \
                 :: "r"(dst), "l"(src))
#define CP_COMMIT() asm volatile("cp.async.commit_group;" ::: "memory")
#define CP_WAIT0()  asm volatile("cp.async.wait_group 0;" ::: "memory")

__device__ __forceinline__ float ldcg_f32(const float* p) {
    float v;
    asm volatile("ld.global.cg.f32 %0, [%1];" : "=f"(v) : "l"(p));
    return v;
}

// ============================================================================
// Kernel 0: convert W1 [256,128] fp32 -> fp16, padded chunk layout.
// ============================================================================
__global__ __launch_bounds__(256) void convW_kernel(const float* __restrict__ W1)
{
    const int idx = blockIdx.x * 256 + threadIdx.x;   // 0..32767
    const int k = idx >> 7;       // H index 0..255
    const int n = idx & 127;      // A index 0..127
    const float w = W1[idx];
    const int chunk = k >> 6;
    const int kc = k & 63;
    const int pos = (chunk * 128 + n) * PADK + kc;
    g_Bh[pos] = __float2half_rn(w);
}

// ============================================================================
// Kernel 1: scores GEMM via single-term fp16 mma.sync.
// NEW: the ENTIRE fp16 B matrix (73.7KB padded) is loaded into smem once in
// the prologue — no per-chunk cp.async waits. Loop: MMA(c) -> convert A(c+1).
// One CTA per 128 tokens; 8 warps, warp tile m32 x n64. 16 MMA/warp/kstep.
// ============================================================================
#define OFF_B     0                     // 4 * 18432 = 73728 bytes (all B)
#define BCHUNK    18432
#define OFF_A     73728                 // 18432 bytes (one A chunk)
#define OFF_B1S   92160
#define OFF_W2S   92672
#define OFF_SRED  93184
#define SMEM_BYTES 94208                // x2 CTAs = 188KB <= 228KB carveout

__global__ __launch_bounds__(256, 2) void scores_mma_kernel(
    const float* __restrict__ X,    // [NTOK, 256]
    const float* __restrict__ b1,   // [128]
    const float* __restrict__ W2,   // [128]
    const float* __restrict__ b2)   // [1]
{
    extern __shared__ __align__(16) char smem[];
    const uint32_t sb = s2u(smem);
    const int tid = threadIdx.x;
    const int wid = tid >> 5;
    const int lane = tid & 31;
    const int tok0 = blockIdx.x * 128;

    const int wm = (wid >> 1) * 32;   // warp M origin (0,32,64,96)
    const int wn = (wid & 1) * 64;    // warp N origin (0,64)

    if (tid < 128) {
        *(float*)(smem + OFF_B1S + tid * 4) = b1[tid];
        *(float*)(smem + OFF_W2S + tid * 4) = W2[tid];
    }

    float acc[2][8][4];
#pragma unroll
    for (int mi = 0; mi < 2; mi++)
#pragma unroll
        for (int nf = 0; nf < 8; nf++)
#pragma unroll
            for (int i = 0; i < 4; i++) acc[mi][nf][i] = 0.0f;

    const int row  = tid >> 1;      // 0..127 (token row in tile)
    const int half = tid & 1;       // 32-col half of the 64-col chunk
    const float4* Xr = (const float4*)(X + (size_t)(tok0 + row) * HH);
    const uint32_t a_boff = (uint32_t)row * (PADK * 2) + (uint32_t)(half * 64);

    const int grp = lane >> 3;
    const uint32_t a_rowl = (uint32_t)((lane & 7) + (grp & 1) * 8);
    const uint32_t a_kad = (uint32_t)((grp >> 1) * 8) * 2;
    const uint32_t b_rowbase = (uint32_t)((lane & 7) + (grp >> 1) * 8);
    const uint32_t b_kad = (uint32_t)((grp & 1) * 8) * 2;

    // ---- prologue: cp.async ALL of B (4608 x 16B), convert A chunk 0 ------
    float4 v[8];
#pragma unroll
    for (int q = 0; q < 8; q++) v[q] = Xr[half * 8 + q];
    {
        const char* srcb = (const char*)g_Bh;
#pragma unroll
        for (int i = 0; i < 18; i++) {
            const int idx = tid + i * 256;
            CP_ASYNC16(sb + OFF_B + idx * 16, srcb + idx * 16);
        }
        CP_COMMIT();
    }
#pragma unroll
    for (int q = 0; q < 8; q++) {
        const float4 vv = v[q];
        const __half2 h0 = __floats2half2_rn(vv.x, vv.y);
        const __half2 h1 = __floats2half2_rn(vv.z, vv.w);
        uint2 hw;
        hw.x = *(const uint32_t*)&h0;
        hw.y = *(const uint32_t*)&h1;
        *(uint2*)(smem + OFF_A + a_boff + (uint32_t)(q * 8)) = hw;
    }
    // preload X for chunk 1
#pragma unroll
    for (int q = 0; q < 8; q++) v[q] = Xr[16 + half * 8 + q];
    CP_WAIT0();
    __syncthreads();

    for (int c = 0; c < 4; c++) {
        const uint32_t b_chunk_base = sb + OFF_B + (uint32_t)c * BCHUNK;

        // ---- 4 k-steps of 16, 16 MMA each (A buffer holds chunk c) ----
#pragma unroll
        for (int ks = 0; ks < 4; ks++) {
            const uint32_t k0b = (uint32_t)(ks * 16) * 2;
            uint32_t ah[2][4];
#pragma unroll
            for (int mi = 0; mi < 2; mi++) {
                const uint32_t a_off =
                    ((uint32_t)(wm + mi * 16) + a_rowl) * (PADK * 2) + k0b + a_kad;
                LDSM_X4(ah[mi][0], ah[mi][1], ah[mi][2], ah[mi][3],
                        sb + OFF_A + a_off);
            }
#pragma unroll
            for (int ng = 0; ng < 4; ng++) {
                const uint32_t b_off =
                    ((uint32_t)(wn + ng * 16) + b_rowbase) * (PADK * 2) + k0b + b_kad;
                uint32_t bh0, bh1, bh2, bh3;
                LDSM_X4(bh0, bh1, bh2, bh3, b_chunk_base + b_off);
#pragma unroll
                for (int mi = 0; mi < 2; mi++) {
                    float* d0 = acc[mi][ng * 2];
                    float* d1 = acc[mi][ng * 2 + 1];
                    MMA_FP16(d0[0], d0[1], d0[2], d0[3],
                             ah[mi][0], ah[mi][1], ah[mi][2], ah[mi][3], bh0, bh1);
                    MMA_FP16(d1[0], d1[1], d1[2], d1[3],
                             ah[mi][0], ah[mi][1], ah[mi][2], ah[mi][3], bh2, bh3);
                }
            }
        }
        __syncthreads();   // all warps done reading A chunk c

        if (c < 3) {
            // convert staged A chunk c+1 into the A buffer
#pragma unroll
            for (int q = 0; q < 8; q++) {
                const float4 vv = v[q];
                const __half2 h0 = __floats2half2_rn(vv.x, vv.y);
                const __half2 h1 = __floats2half2_rn(vv.z, vv.w);
                uint2 hw;
                hw.x = *(const uint32_t*)&h0;
                hw.y = *(const uint32_t*)&h1;
                *(uint2*)(smem + OFF_A + a_boff + (uint32_t)(q * 8)) = hw;
            }
            if (c < 2) {
#pragma unroll
                for (int q = 0; q < 8; q++)
                    v[q] = Xr[(c + 2) * 16 + half * 8 + q];
            }
            __syncthreads();   // A chunk c+1 ready
        }
    }

    // ---- epilogue: tanh dot W2 over warp's 64 cols, then cross-warp add ----
    float* sred = (float*)(smem + OFF_SRED);   // [2][128]
#pragma unroll
    for (int mi = 0; mi < 2; mi++) {
        float s0 = 0.0f, s1 = 0.0f;
#pragma unroll
        for (int nf = 0; nf < 8; nf++) {
            const int c0 = wn + nf * 8 + (lane & 3) * 2;
            const float bb0 = *(const float*)(smem + OFF_B1S + c0 * 4);
            const float bb1v = *(const float*)(smem + OFF_B1S + (c0 + 1) * 4);
            const float ww0 = *(const float*)(smem + OFF_W2S + c0 * 4);
            const float ww1 = *(const float*)(smem + OFF_W2S + (c0 + 1) * 4);
            s0 += tanhf(acc[mi][nf][0] + bb0) * ww0 +
                  tanhf(acc[mi][nf][1] + bb1v) * ww1;
            s1 += tanhf(acc[mi][nf][2] + bb0) * ww0 +
                  tanhf(acc[mi][nf][3] + bb1v) * ww1;
        }
        s0 += __shfl_xor_sync(0xffffffffu, s0, 1);
        s0 += __shfl_xor_sync(0xffffffffu, s0, 2);
        s1 += __shfl_xor_sync(0xffffffffu, s1, 1);
        s1 += __shfl_xor_sync(0xffffffffu, s1, 2);
        if ((lane & 3) == 0) {
            const int r = wm + mi * 16 + (lane >> 2);
            sred[(wid & 1) * 128 + r]     = s0;
            sred[(wid & 1) * 128 + r + 8] = s1;
        }
    }
    __syncthreads();
    if (tid < 128)
        g_scores[tok0 + tid] = sred[tid] + sred[128 + tid] + b2[0];
}

// ============================================================================
// Kernel 2: entmax-1.5 per batch row via fixed-count bisection (no sort)
// + deterministic support compaction to global. Also resets g_ctr[b].
// ============================================================================
__global__ __launch_bounds__(512) void entmax_kernel(float* __restrict__ weights)
{
    const int b = blockIdx.x;
    const int tid = threadIdx.x;
    const int wid = tid >> 5;
    const int lane = tid & 31;

    __shared__ float red[16];
    __shared__ float s_bc;
    __shared__ int iscan[512];

    if (tid == 0) g_ctr[b] = 0;     // reset ctx arrival counter each replay

    const float* sc = g_scores + (size_t)b * SS;
    const int base = tid * 8;

    float z[8];
    {
        const float4 p0 = ((const float4*)sc)[tid * 2];
        const float4 p1 = ((const float4*)sc)[tid * 2 + 1];
        z[0] = 0.5f * p0.x; z[1] = 0.5f * p0.y;
        z[2] = 0.5f * p0.z; z[3] = 0.5f * p0.w;
        z[4] = 0.5f * p1.x; z[5] = 0.5f * p1.y;
        z[6] = 0.5f * p1.z; z[7] = 0.5f * p1.w;
    }

    float m = z[0];
#pragma unroll
    for (int j = 1; j < 8; j++) m = fmaxf(m, z[j]);
#pragma unroll
    for (int o = 16; o > 0; o >>= 1) m = fmaxf(m, __shfl_xor_sync(0xffffffffu, m, o));
    if (lane == 0) red[wid] = m;
    __syncthreads();
    if (tid == 0) {
        float t = red[0];
#pragma unroll
        for (int i = 1; i < 16; i++) t = fmaxf(t, red[i]);
        s_bc = t;
    }
    __syncthreads();
    const float mx = s_bc;
#pragma unroll
    for (int j = 0; j < 8; j++) z[j] -= mx;

    // bisection, 24 iterations: |tau error| <= 2^-24 ~ 6e-8 (weights ~1e-7)
    float lo = -1.0f, hi = 0.0f;
    for (int it = 0; it < 24; it++) {
        const float mid = 0.5f * (lo + hi);
        float s = 0.0f;
#pragma unroll
        for (int j = 0; j < 8; j++) {
            float d = z[j] - mid;
            d = d > 0.0f ? d : 0.0f;
            s = fmaf(d, d, s);
        }
#pragma unroll
        for (int o = 16; o > 0; o >>= 1) s += __shfl_xor_sync(0xffffffffu, s, o);
        if (lane == 0) red[wid] = s;
        __syncthreads();
        float tot = 0.0f;
#pragma unroll
        for (int i = 0; i < 16; i++) tot += red[i];
        __syncthreads();
        if (tot >= 1.0f) lo = mid; else hi = mid;
    }
    const float tau = 0.5f * (lo + hi);

    float* wout = weights + (size_t)b * SS;
    float wv[8];
    int mycnt = 0;
#pragma unroll
    for (int j = 0; j < 8; j++) {
        float d = z[j] - tau;
        d = d > 0.0f ? d : 0.0f;
        const float w = d * d;
        wv[j] = w;
        wout[base + j] = w;
        if (w > 0.0f) mycnt++;
    }
    iscan[tid] = mycnt;
    __syncthreads();
    for (int off = 1; off < 512; off <<= 1) {
        int a = 0;
        if (tid >= off) a = iscan[tid - off];
        __syncthreads();
        iscan[tid] += a;
        __syncthreads();
    }
    int pos = iscan[tid] - mycnt;
#pragma unroll
    for (int j = 0; j < 8; j++) {
        if (wv[j] > 0.0f) {
            g_nzidx[(size_t)b * SS + pos] = base + j;
            g_nzw[(size_t)b * SS + pos]   = wv[j];
            pos++;
        }
    }
    if (tid == 511) g_nzcnt[b] = iscan[511];
}

// ============================================================================
// Kernel 3: sparse context partials + last-block fused reduce.
// grid (B, NPART), 256 threads (one per h).
// ============================================================================
__global__ __launch_bounds__(256) void ctx_sparse_kernel(
    const float* __restrict__ X, float* __restrict__ ctx)
{
    const int b = blockIdx.x;
    const int sl = blockIdx.y;
    const int h = threadIdx.x;

    __shared__ int   sidx[576];
    __shared__ float swt[576];
    __shared__ int   s_last;

    const int cnt = g_nzcnt[b];
    const int per = (cnt + NPART - 1) / NPART;
    const int s0 = sl * per;
    int s1 = s0 + per; if (s1 > cnt) s1 = cnt;
    const int n = s1 - s0;

    for (int t = h; t < n; t += 256) {
        sidx[t] = g_nzidx[(size_t)b * SS + s0 + t];
        swt[t]  = g_nzw[(size_t)b * SS + s0 + t];
    }
    __syncthreads();

    const float* Xb = X + (size_t)b * SS * HH;
    float acc = 0.0f;
    int i = 0;
    for (; i + 8 <= n; i += 8) {
        float x[8];
#pragma unroll
        for (int j = 0; j < 8; j++)
            x[j] = Xb[(size_t)sidx[i + j] * HH + h];
#pragma unroll
        for (int j = 0; j < 8; j++)
            acc = fmaf(x[j], swt[i + j], acc);
    }
    for (; i < n; i++)
        acc = fmaf(Xb[(size_t)sidx[i] * HH + h], swt[i], acc);

    g_partial[((size_t)b * NPART + sl) * HH + h] = acc;

    // last-arriving block for this batch reduces all NPART partials
    __threadfence();
    __syncthreads();
    if (h == 0) {
        const int old = atomicAdd(&g_ctr[b], 1);
        s_last = (old == NPART - 1) ? 1 : 0;
    }
    __syncthreads();
    if (s_last) {
        float s = 0.0f;
#pragma unroll
        for (int c = 0; c < NPART; c++)
            s += ldcg_f32(&g_partial[((size_t)b * NPART + c) * HH + h]);
        ctx[(size_t)b * HH + h] = s;
    }
}

// ============================================================================
extern "C" void kernel_launch(void* const* d_in, const int* in_sizes, int n_in,
                              void* d_out, int out_size)
{
    const float* X  = (const float*)d_in[0];   // [64,4096,256]
    const float* W1 = (const float*)d_in[1];   // [256,128]
    const float* b1 = (const float*)d_in[2];   // [128]
    const float* W2 = (const float*)d_in[3];   // [128,1]
    const float* b2 = (const float*)d_in[4];   // [1]

    float* out = (float*)d_out;
    float* ctx = out;                 // [64,256]  (tuple elem 0)
    float* wts = out + BB * HH;       // [64,4096] (tuple elem 1)

    cudaFuncSetAttribute(scores_mma_kernel,
                         cudaFuncAttributeMaxDynamicSharedMemorySize, SMEM_BYTES);

    convW_kernel<<<128, 256>>>(W1);
    scores_mma_kernel<<<NTOK / 128, 256, SMEM_BYTES>>>(X, b1, W2, b2);
    entmax_kernel<<<BB, 512>>>(wts);
    ctx_sparse_kernel<<<dim3(BB, NPART), 256>>>(X, ctx);
}